// round 1
// baseline (speedup 1.0000x reference)
#include <cuda_runtime.h>
#include <cstdint>

// Problem constants
#define N_ROWS 8192
#define DIMS   2048
#define CHUNK  8
#define GROUP  4
// GEMM tiling
#define TM 64
#define TN 64
#define TK 16
#define NB (N_ROWS / TM)   // 128 blocks per dim

// Scratch (no cudaMalloc allowed)
__device__ unsigned long long g_best[N_ROWS];
__device__ float g_dap[N_ROWS];

__device__ __forceinline__ unsigned long long packCand(float v, unsigned j) {
    unsigned u = __float_as_uint(v);
    u = (u & 0x80000000u) ? ~u : (u | 0x80000000u);
    // invert index so that at equal value the SMALLER index wins the max
    return ((unsigned long long)u << 32) | (unsigned long long)(0xFFFFFFFFu - j);
}

// ---------------------------------------------------------------------------
// Kernel 0: init scratch + zero output scalar
// ---------------------------------------------------------------------------
__global__ void initKernel(float* out) {
    int i = blockIdx.x * blockDim.x + threadIdx.x;
    if (i < N_ROWS) g_best[i] = 0ull;   // ordered-float 0 == most-negative
    if (i == 0) out[0] = 0.0f;
}

// ---------------------------------------------------------------------------
// Kernel 1: chunk centers + d_ap per row
// d_ap_i = 0.5 * mean_d | x_id - center_d |
// One block per chunk of 8 rows.
// ---------------------------------------------------------------------------
__global__ void centersDapKernel(const float* __restrict__ x) {
    int c = blockIdx.x;                       // chunk id, 0..1023
    const float4* base = (const float4*)(x + (size_t)c * CHUNK * DIMS);
    const int D4 = DIMS / 4;                  // 512 float4 per row

    float acc[CHUNK];
    #pragma unroll
    for (int r = 0; r < CHUNK; r++) acc[r] = 0.0f;

    for (int col = threadIdx.x; col < D4; col += blockDim.x) {
        float4 v[CHUNK];
        float4 m = make_float4(0.f, 0.f, 0.f, 0.f);
        #pragma unroll
        for (int r = 0; r < CHUNK; r++) {
            v[r] = base[r * (DIMS / 4) + col];
            m.x += v[r].x; m.y += v[r].y; m.z += v[r].z; m.w += v[r].w;
        }
        m.x *= 0.125f; m.y *= 0.125f; m.z *= 0.125f; m.w *= 0.125f;
        #pragma unroll
        for (int r = 0; r < CHUNK; r++) {
            acc[r] += fabsf(v[r].x - m.x) + fabsf(v[r].y - m.y)
                    + fabsf(v[r].z - m.z) + fabsf(v[r].w - m.w);
        }
    }

    __shared__ float part[CHUNK][8];
    int lane = threadIdx.x & 31, w = threadIdx.x >> 5;
    #pragma unroll
    for (int r = 0; r < CHUNK; r++) {
        float s = acc[r];
        #pragma unroll
        for (int off = 16; off; off >>= 1) s += __shfl_xor_sync(0xFFFFFFFFu, s, off);
        if (lane == 0) part[r][w] = s;
    }
    __syncthreads();
    if (threadIdx.x < CHUNK) {
        float s = 0.f;
        #pragma unroll
        for (int ww = 0; ww < 8; ww++) s += part[threadIdx.x][ww];
        g_dap[c * CHUNK + threadIdx.x] = 0.5f * s * (1.0f / DIMS);
    }
}

// ---------------------------------------------------------------------------
// Kernel 2: symmetric sim = x @ x^T with fused masked argmax.
// Upper-triangular 64x64 block grid; each block updates row-side and
// (off-diagonal) column-side running (max,argmax) via packed atomicMax.
// ---------------------------------------------------------------------------
__global__ __launch_bounds__(256, 4) void simArgmaxKernel(const float* __restrict__ x) {
    const int bi = blockIdx.y, bj = blockIdx.x;
    if (bj < bi) return;

    __shared__ float As[TK][TM];
    __shared__ float Bs[TK][TN];
    __shared__ unsigned long long colbest[TN][16];

    const int tid = threadIdx.x;     // 256 threads
    const int tx = tid & 15;         // 0..15  -> column quad
    const int ty = tid >> 4;         // 0..15  -> row quad

    float acc[4][4];
    #pragma unroll
    for (int i = 0; i < 4; i++)
        #pragma unroll
        for (int j = 0; j < 4; j++) acc[i][j] = 0.0f;

    const int lrow = tid >> 2;            // 0..63
    const int lk4  = (tid & 3) * 4;       // 0,4,8,12
    const float* arow = x + (size_t)(bi * TM + lrow) * DIMS;
    const float* brow = x + (size_t)(bj * TN + lrow) * DIMS;

    for (int k0 = 0; k0 < DIMS; k0 += TK) {
        float4 a = *(const float4*)(arow + k0 + lk4);
        float4 b = *(const float4*)(brow + k0 + lk4);
        __syncthreads();
        As[lk4 + 0][lrow] = a.x; As[lk4 + 1][lrow] = a.y;
        As[lk4 + 2][lrow] = a.z; As[lk4 + 3][lrow] = a.w;
        Bs[lk4 + 0][lrow] = b.x; Bs[lk4 + 1][lrow] = b.y;
        Bs[lk4 + 2][lrow] = b.z; Bs[lk4 + 3][lrow] = b.w;
        __syncthreads();
        #pragma unroll
        for (int kk = 0; kk < TK; kk++) {
            float4 av = *(const float4*)(&As[kk][ty * 4]);
            float4 bv = *(const float4*)(&Bs[kk][tx * 4]);
            float aa[4] = {av.x, av.y, av.z, av.w};
            float bb[4] = {bv.x, bv.y, bv.z, bv.w};
            #pragma unroll
            for (int i = 0; i < 4; i++)
                #pragma unroll
                for (int j = 0; j < 4; j++)
                    acc[i][j] = fmaf(aa[i], bb[j], acc[i][j]);
        }
    }

    const bool diag = (bi == bj);

    // ---- row-side: for each of my 4 rows, max over my 4 cols, then over tx
    #pragma unroll
    for (int i = 0; i < 4; i++) {
        const int gi = bi * TM + ty * 4 + i;
        float bv = -__int_as_float(0x7F800000);   // -inf
        unsigned bidx = 0;
        #pragma unroll
        for (int j = 0; j < 4; j++) {
            const int gj = bj * TN + tx * 4 + j;
            float v = acc[i][j];
            if (diag && ((gi >> 2) == (gj >> 2))) v = -__int_as_float(0x7F800000);
            if (v > bv) { bv = v; bidx = (unsigned)gj; }
        }
        unsigned long long p = packCand(bv, bidx);
        #pragma unroll
        for (int off = 8; off; off >>= 1) {
            unsigned long long q = __shfl_xor_sync(0xFFFFFFFFu, p, off);
            if (q > p) p = q;
        }
        if (tx == 0) atomicMax(&g_best[gi], p);
    }

    // ---- column-side (symmetry): skip on diagonal (redundant)
    if (!diag) {
        #pragma unroll
        for (int j = 0; j < 4; j++) {
            float bv = -__int_as_float(0x7F800000);
            unsigned bidx = 0;
            #pragma unroll
            for (int i = 0; i < 4; i++) {
                float v = acc[i][j];
                if (v > bv) { bv = v; bidx = (unsigned)(bi * TM + ty * 4 + i); }
            }
            colbest[tx * 4 + j][ty] = packCand(bv, bidx);
        }
        __syncthreads();
        if (tid < TN) {
            unsigned long long p = colbest[tid][0];
            #pragma unroll
            for (int t = 1; t < 16; t++) {
                unsigned long long q = colbest[tid][t];
                if (q > p) p = q;
            }
            atomicMax(&g_best[bj * TN + tid], p);
        }
    }
}

// ---------------------------------------------------------------------------
// Kernel 3: gather x_neg, d_an, final weighted sum
// One block per row.
// ---------------------------------------------------------------------------
__global__ void finalKernel(const float* __restrict__ x, float* __restrict__ out) {
    const int i = blockIdx.x;
    const unsigned j = 0xFFFFFFFFu - (unsigned)(g_best[i] & 0xFFFFFFFFull);

    const float4* xi = (const float4*)(x + (size_t)i * DIMS);
    const float4* xj = (const float4*)(x + (size_t)j * DIMS);
    const int D4 = DIMS / 4;

    float s = 0.0f;
    for (int c = threadIdx.x; c < D4; c += blockDim.x) {
        float4 a = xi[c];
        float4 b = xj[c];
        s += fabsf(a.x - b.x) + fabsf(a.y - b.y) + fabsf(a.z - b.z) + fabsf(a.w - b.w);
    }

    __shared__ float part[8];
    int lane = threadIdx.x & 31, w = threadIdx.x >> 5;
    #pragma unroll
    for (int off = 16; off; off >>= 1) s += __shfl_xor_sync(0xFFFFFFFFu, s, off);
    if (lane == 0) part[w] = s;
    __syncthreads();
    if (threadIdx.x == 0) {
        float tot = 0.f;
        #pragma unroll
        for (int ww = 0; ww < 8; ww++) tot += part[ww];
        float dan = tot * (1.0f / DIMS);
        atomicAdd(out, 0.125f * g_dap[i] / (dan + 1e-7f));
    }
}

// ---------------------------------------------------------------------------
extern "C" void kernel_launch(void* const* d_in, const int* in_sizes, int n_in,
                              void* d_out, int out_size) {
    const float* x = (const float*)d_in[0];
    float* out = (float*)d_out;

    initKernel<<<(N_ROWS + 255) / 256, 256>>>(out);
    centersDapKernel<<<N_ROWS / CHUNK, 256>>>(x);
    dim3 grid(NB, NB);
    simArgmaxKernel<<<grid, 256>>>(x);
    finalKernel<<<N_ROWS, 256>>>(x, out);
}

// round 4
// speedup vs baseline: 4.0149x; 4.0149x over previous
#include <cuda_runtime.h>
#include <cuda_bf16.h>
#include <cstdint>

// ---------------------------------------------------------------- constants
#define N_ROWS 8192
#define DIMS   2048
#define CHUNK  8
#define TM 128
#define TN 128
#define KC 64                     // K per smem stage (4 mma k-steps of 16)
#define NB (N_ROWS / TM)          // 64
#define NCHUNK (DIMS / KC)        // 32

#define TILE_B  (128 * 128)       // 16 KB: 128 rows x 64 bf16 (128B) per operand
#define STAGE_B (4 * TILE_B)      // Ahi, Alo, Bhi, Blo = 64 KB
#define SMEM_TOTAL (2 * STAGE_B)  // 128 KB double-buffered

#define NEG_INF __int_as_float(0xFF800000)

// ---------------------------------------------------------------- scratch
__device__ unsigned long long g_best[N_ROWS];
__device__ float g_dap[N_ROWS];
__device__ __nv_bfloat16 g_xhi[(size_t)N_ROWS * DIMS];
__device__ __nv_bfloat16 g_xlo[(size_t)N_ROWS * DIMS];

// ---------------------------------------------------------------- helpers
__device__ __forceinline__ uint32_t smem_u32(const void* p) {
    uint32_t a;
    asm("{ .reg .u64 t; cvta.to.shared.u64 t, %1; cvt.u32.u64 %0, t; }" : "=r"(a) : "l"(p));
    return a;
}
__device__ __forceinline__ unsigned long long packCand(float v, unsigned j) {
    unsigned u = __float_as_uint(v);
    u = (u & 0x80000000u) ? ~u : (u | 0x80000000u);
    return ((unsigned long long)u << 32) | (unsigned long long)(0xFFFFFFFFu - j);
}
__device__ __forceinline__ void cpasync16(uint32_t dst, const void* src) {
    asm volatile("cp.async.cg.shared.global [%0], [%1], 16;" :: "r"(dst), "l"(src) : "memory");
}
__device__ __forceinline__ void ldsm_x4(uint32_t* r, uint32_t addr) {
    asm volatile("ldmatrix.sync.aligned.m8n8.x4.shared.b16 {%0,%1,%2,%3}, [%4];"
                 : "=r"(r[0]), "=r"(r[1]), "=r"(r[2]), "=r"(r[3]) : "r"(addr));
}
__device__ __forceinline__ void mma16816(float* d, const uint32_t* a, const uint32_t* b) {
    asm volatile(
        "mma.sync.aligned.m16n8k16.row.col.f32.bf16.bf16.f32 "
        "{%0,%1,%2,%3}, {%4,%5,%6,%7}, {%8,%9}, {%0,%1,%2,%3};"
        : "+f"(d[0]), "+f"(d[1]), "+f"(d[2]), "+f"(d[3])
        : "r"(a[0]), "r"(a[1]), "r"(a[2]), "r"(a[3]), "r"(b[0]), "r"(b[1]));
}
// swizzled smem byte offset: 128B rows, 8x 16B chunks, XOR by row&7
__device__ __forceinline__ uint32_t swz(int row, int chunk) {
    return (uint32_t)(row * 128 + ((chunk ^ (row & 7)) << 4));
}

// ---------------------------------------------------------------- kernel 0
__global__ void initKernel(float* out) {
    int i = blockIdx.x * blockDim.x + threadIdx.x;
    if (i < N_ROWS) g_best[i] = 0ull;
    if (i == 0) out[0] = 0.0f;
}

// ---------------------------------------------------------------- kernel 1: fp32 -> bf16 hi/lo
__global__ void convertKernel(const float* __restrict__ x) {
    size_t i = (size_t)blockIdx.x * blockDim.x + threadIdx.x;
    const size_t n4 = (size_t)N_ROWS * DIMS / 4;
    if (i >= n4) return;
    float4 v = ((const float4*)x)[i];
    __nv_bfloat16 h0 = __float2bfloat16(v.x), h1 = __float2bfloat16(v.y);
    __nv_bfloat16 h2 = __float2bfloat16(v.z), h3 = __float2bfloat16(v.w);
    __nv_bfloat16 l0 = __float2bfloat16(v.x - __bfloat162float(h0));
    __nv_bfloat16 l1 = __float2bfloat16(v.y - __bfloat162float(h1));
    __nv_bfloat16 l2 = __float2bfloat16(v.z - __bfloat162float(h2));
    __nv_bfloat16 l3 = __float2bfloat16(v.w - __bfloat162float(h3));
    ushort4 hp, lp;
    hp.x = *(unsigned short*)&h0; hp.y = *(unsigned short*)&h1;
    hp.z = *(unsigned short*)&h2; hp.w = *(unsigned short*)&h3;
    lp.x = *(unsigned short*)&l0; lp.y = *(unsigned short*)&l1;
    lp.z = *(unsigned short*)&l2; lp.w = *(unsigned short*)&l3;
    ((ushort4*)g_xhi)[i] = hp;
    ((ushort4*)g_xlo)[i] = lp;
}

// ---------------------------------------------------------------- kernel 2: centers + d_ap
__global__ void centersDapKernel(const float* __restrict__ x) {
    int c = blockIdx.x;
    const float4* base = (const float4*)(x + (size_t)c * CHUNK * DIMS);
    const int D4 = DIMS / 4;

    float acc[CHUNK];
    #pragma unroll
    for (int r = 0; r < CHUNK; r++) acc[r] = 0.0f;

    for (int col = threadIdx.x; col < D4; col += blockDim.x) {
        float4 v[CHUNK];
        float4 m = make_float4(0.f, 0.f, 0.f, 0.f);
        #pragma unroll
        for (int r = 0; r < CHUNK; r++) {
            v[r] = base[r * (DIMS / 4) + col];
            m.x += v[r].x; m.y += v[r].y; m.z += v[r].z; m.w += v[r].w;
        }
        m.x *= 0.125f; m.y *= 0.125f; m.z *= 0.125f; m.w *= 0.125f;
        #pragma unroll
        for (int r = 0; r < CHUNK; r++) {
            acc[r] += fabsf(v[r].x - m.x) + fabsf(v[r].y - m.y)
                    + fabsf(v[r].z - m.z) + fabsf(v[r].w - m.w);
        }
    }

    __shared__ float part[CHUNK][8];
    int lane = threadIdx.x & 31, w = threadIdx.x >> 5;
    #pragma unroll
    for (int r = 0; r < CHUNK; r++) {
        float s = acc[r];
        #pragma unroll
        for (int off = 16; off; off >>= 1) s += __shfl_xor_sync(0xFFFFFFFFu, s, off);
        if (lane == 0) part[r][w] = s;
    }
    __syncthreads();
    if (threadIdx.x < CHUNK) {
        float s = 0.f;
        #pragma unroll
        for (int ww = 0; ww < 8; ww++) s += part[threadIdx.x][ww];
        g_dap[c * CHUNK + threadIdx.x] = 0.5f * s * (1.0f / DIMS);
    }
}

// ---------------------------------------------------------------- kernel 3: HMMA sim + fused argmax
__device__ __forceinline__ void fill_stage(uint32_t sbase, int rowA, int rowB,
                                           int k0, int tid) {
    const __nv_bfloat16* srcs[4] = {
        g_xhi + (size_t)rowA * DIMS, g_xlo + (size_t)rowA * DIMS,
        g_xhi + (size_t)rowB * DIMS, g_xlo + (size_t)rowB * DIMS };
    #pragma unroll
    for (int o = 0; o < 4; o++) {
        uint32_t base = sbase + o * TILE_B;
        const char* g = (const char*)(srcs[o]) + (size_t)k0 * 2;
        #pragma unroll
        for (int c = tid; c < 1024; c += 256) {
            int row = c >> 3, ch = c & 7;
            cpasync16(base + swz(row, ch), g + (size_t)row * (DIMS * 2) + ch * 16);
        }
    }
}

__global__ __launch_bounds__(256, 1) void simArgmaxMma() {
    const int bi = blockIdx.y, bj = blockIdx.x;
    if (bj < bi) return;
    const bool diag = (bi == bj);

    extern __shared__ char smem[];
    const uint32_t sb = smem_u32(smem);
    const int tid = threadIdx.x;
    const int lane = tid & 31, warp = tid >> 5;
    const int wr = warp >> 1, wc = warp & 1;   // 4 x 2 warp grid, warp tile 32x64

    const int rowA = bi * TM, rowB = bj * TN;

    float acc[2][8][4];
    #pragma unroll
    for (int mt = 0; mt < 2; mt++)
        #pragma unroll
        for (int nt = 0; nt < 8; nt++)
            #pragma unroll
            for (int e = 0; e < 4; e++) acc[mt][nt][e] = 0.0f;

    // ldmatrix lane decomposition
    const int mi = lane >> 3, r8 = lane & 7;

    fill_stage(sb, rowA, rowB, 0, tid);
    asm volatile("cp.async.commit_group;" ::: "memory");

    #pragma unroll 1
    for (int t = 0; t < NCHUNK; t++) {
        if (t + 1 < NCHUNK) {
            fill_stage(sb + ((t + 1) & 1) * STAGE_B, rowA, rowB, (t + 1) * KC, tid);
            asm volatile("cp.async.commit_group;" ::: "memory");
            asm volatile("cp.async.wait_group 1;" ::: "memory");
        } else {
            asm volatile("cp.async.wait_group 0;" ::: "memory");
        }
        __syncthreads();

        const uint32_t stg = sb + (t & 1) * STAGE_B;
        const uint32_t sAhi = stg, sAlo = stg + TILE_B;
        const uint32_t sBhi = stg + 2 * TILE_B, sBlo = stg + 3 * TILE_B;

        #pragma unroll
        for (int ks = 0; ks < 4; ks++) {
            const int chunk = ks * 2 + (mi >> 1);
            uint32_t ahi[2][4], alo[2][4], bhi[8][2], blo[8][2];
            #pragma unroll
            for (int mt = 0; mt < 2; mt++) {
                int row = wr * 32 + mt * 16 + (mi & 1) * 8 + r8;
                ldsm_x4(ahi[mt], sAhi + swz(row, chunk));
                ldsm_x4(alo[mt], sAlo + swz(row, chunk));
            }
            #pragma unroll
            for (int np = 0; np < 4; np++) {
                int row = wc * 64 + np * 16 + (mi & 1) * 8 + r8;
                uint32_t th[4], tl[4];
                ldsm_x4(th, sBhi + swz(row, chunk));
                ldsm_x4(tl, sBlo + swz(row, chunk));
                bhi[2 * np][0] = th[0]; bhi[2 * np + 1][0] = th[1];
                bhi[2 * np][1] = th[2]; bhi[2 * np + 1][1] = th[3];
                blo[2 * np][0] = tl[0]; blo[2 * np + 1][0] = tl[1];
                blo[2 * np][1] = tl[2]; blo[2 * np + 1][1] = tl[3];
            }
            #pragma unroll
            for (int mt = 0; mt < 2; mt++)
                #pragma unroll
                for (int nt = 0; nt < 8; nt++) {
                    mma16816(acc[mt][nt], ahi[mt], bhi[nt]);
                    mma16816(acc[mt][nt], ahi[mt], blo[nt]);
                    mma16816(acc[mt][nt], alo[mt], bhi[nt]);
                }
        }
        __syncthreads();
    }

    // ---------------- epilogue ----------------
    const int qrow = lane >> 2;            // 0..7
    const int qcol = (lane & 3) * 2;       // 0,2,4,6

    // row-side argmax (rows of A tile)
    #pragma unroll
    for (int mt = 0; mt < 2; mt++)
        #pragma unroll
        for (int half = 0; half < 2; half++) {
            const int gi = rowA + wr * 32 + mt * 16 + half * 8 + qrow;
            float bv = NEG_INF;
            unsigned bj_ = 0;
            #pragma unroll
            for (int nt = 0; nt < 8; nt++)
                #pragma unroll
                for (int e = 0; e < 2; e++) {
                    const int gj = rowB + wc * 64 + nt * 8 + qcol + e;
                    float v = acc[mt][nt][half * 2 + e];
                    if (diag && ((gi >> 2) == (gj >> 2))) v = NEG_INF;
                    if (v > bv) { bv = v; bj_ = (unsigned)gj; }
                }
            unsigned long long p = packCand(bv, bj_);
            #pragma unroll
            for (int off = 1; off <= 2; off <<= 1) {
                unsigned long long q = __shfl_xor_sync(0xFFFFFFFFu, p, off);
                if (q > p) p = q;
            }
            if ((lane & 3) == 0) atomicMax(&g_best[gi], p);
        }

    // column-side (symmetry), off-diagonal tiles only
    if (!diag) {
        unsigned long long* colred = (unsigned long long*)smem;   // 128 cols x 4 warpRows
        #pragma unroll
        for (int nt = 0; nt < 8; nt++)
            #pragma unroll
            for (int e = 0; e < 2; e++) {
                float bv = NEG_INF;
                unsigned br = 0;
                #pragma unroll
                for (int mt = 0; mt < 2; mt++)
                    #pragma unroll
                    for (int half = 0; half < 2; half++) {
                        const int gi = rowA + wr * 32 + mt * 16 + half * 8 + qrow;
                        float v = acc[mt][nt][half * 2 + e];
                        if (v > bv) { bv = v; br = (unsigned)gi; }
                    }
                unsigned long long p = packCand(bv, br);
                #pragma unroll
                for (int off = 4; off <= 16; off <<= 1) {
                    unsigned long long q = __shfl_xor_sync(0xFFFFFFFFu, p, off);
                    if (q > p) p = q;
                }
                if (qrow == 0) {
                    const int lc = wc * 64 + nt * 8 + qcol + e;
                    colred[lc * 4 + wr] = p;
                }
            }
        __syncthreads();
        if (tid < 128) {
            unsigned long long p = colred[tid * 4];
            #pragma unroll
            for (int w = 1; w < 4; w++) {
                unsigned long long q = colred[tid * 4 + w];
                if (q > p) p = q;
            }
            atomicMax(&g_best[rowB + tid], p);
        }
    }
}

// ---------------------------------------------------------------- kernel 4: final
__global__ void finalKernel(const float* __restrict__ x, float* __restrict__ out) {
    const int i = blockIdx.x;
    const unsigned j = 0xFFFFFFFFu - (unsigned)(g_best[i] & 0xFFFFFFFFull);

    const float4* xi = (const float4*)(x + (size_t)i * DIMS);
    const float4* xj = (const float4*)(x + (size_t)j * DIMS);
    const int D4 = DIMS / 4;

    float s = 0.0f;
    for (int c = threadIdx.x; c < D4; c += blockDim.x) {
        float4 a = xi[c];
        float4 b = xj[c];
        s += fabsf(a.x - b.x) + fabsf(a.y - b.y) + fabsf(a.z - b.z) + fabsf(a.w - b.w);
    }

    __shared__ float part[8];
    int lane = threadIdx.x & 31, w = threadIdx.x >> 5;
    #pragma unroll
    for (int off = 16; off; off >>= 1) s += __shfl_xor_sync(0xFFFFFFFFu, s, off);
    if (lane == 0) part[w] = s;
    __syncthreads();
    if (threadIdx.x == 0) {
        float tot = 0.f;
        #pragma unroll
        for (int ww = 0; ww < 8; ww++) tot += part[ww];
        float dan = tot * (1.0f / DIMS);
        atomicAdd(out, 0.125f * g_dap[i] / (dan + 1e-7f));
    }
}

// ----------------------------------------------------------------
extern "C" void kernel_launch(void* const* d_in, const int* in_sizes, int n_in,
                              void* d_out, int out_size) {
    const float* x = (const float*)d_in[0];
    float* out = (float*)d_out;

    static int configured = 0;
    cudaFuncSetAttribute(simArgmaxMma, cudaFuncAttributeMaxDynamicSharedMemorySize,
                         SMEM_TOTAL);
    (void)configured;

    initKernel<<<(N_ROWS + 255) / 256, 256>>>(out);
    convertKernel<<<(N_ROWS * (DIMS / 4) + 255) / 256, 256>>>(x);
    centersDapKernel<<<N_ROWS / CHUNK, 256>>>(x);
    dim3 grid(NB, NB);
    simArgmaxMma<<<grid, 256, SMEM_TOTAL>>>();
    finalKernel<<<N_ROWS, 256>>>(x, out);
}

// round 5
// speedup vs baseline: 4.1828x; 1.0418x over previous
#include <cuda_runtime.h>
#include <cuda_bf16.h>
#include <cstdint>

// ---------------------------------------------------------------- constants
#define N_ROWS 8192
#define DIMS   2048
#define CHUNK  8
#define TM 128
#define TN 128
#define KC 64                     // K per smem stage (4 mma k-steps of 16)
#define NB (N_ROWS / TM)          // 64
#define NCHUNK (DIMS / KC)        // 32
#define NTILES (NB * (NB + 1) / 2)  // 2080 upper-triangular tiles

#define TILE_B  (128 * 128)       // 16 KB: 128 rows x 64 bf16 (128B)
#define STAGE_B (3 * TILE_B)      // Ahi, Bhi, Blo = 48 KB
#define SMEM_TOTAL (2 * STAGE_B)  // 96 KB double-buffered -> 2 CTAs/SM

#define NEG_INF __int_as_float(0xFF800000)

// ---------------------------------------------------------------- scratch
__device__ unsigned long long g_best[N_ROWS];
__device__ float g_dap[N_ROWS];
__device__ __nv_bfloat16 g_xhi[(size_t)N_ROWS * DIMS];
__device__ __nv_bfloat16 g_xlo[(size_t)N_ROWS * DIMS];

// ---------------------------------------------------------------- helpers
__device__ __forceinline__ uint32_t smem_u32(const void* p) {
    uint32_t a;
    asm("{ .reg .u64 t; cvta.to.shared.u64 t, %1; cvt.u32.u64 %0, t; }" : "=r"(a) : "l"(p));
    return a;
}
__device__ __forceinline__ unsigned long long packCand(float v, unsigned j) {
    unsigned u = __float_as_uint(v);
    u = (u & 0x80000000u) ? ~u : (u | 0x80000000u);
    return ((unsigned long long)u << 32) | (unsigned long long)(0xFFFFFFFFu - j);
}
__device__ __forceinline__ void cpasync16(uint32_t dst, const void* src) {
    asm volatile("cp.async.cg.shared.global [%0], [%1], 16;" :: "r"(dst), "l"(src) : "memory");
}
__device__ __forceinline__ void ldsm_x4(uint32_t* r, uint32_t addr) {
    asm volatile("ldmatrix.sync.aligned.m8n8.x4.shared.b16 {%0,%1,%2,%3}, [%4];"
                 : "=r"(r[0]), "=r"(r[1]), "=r"(r[2]), "=r"(r[3]) : "r"(addr));
}
__device__ __forceinline__ void mma16816(float* d, const uint32_t* a, const uint32_t* b) {
    asm volatile(
        "mma.sync.aligned.m16n8k16.row.col.f32.bf16.bf16.f32 "
        "{%0,%1,%2,%3}, {%4,%5,%6,%7}, {%8,%9}, {%0,%1,%2,%3};"
        : "+f"(d[0]), "+f"(d[1]), "+f"(d[2]), "+f"(d[3])
        : "r"(a[0]), "r"(a[1]), "r"(a[2]), "r"(a[3]), "r"(b[0]), "r"(b[1]));
}
// swizzled smem byte offset: 128B rows, 8x 16B chunks, XOR by row&7
__device__ __forceinline__ uint32_t swz(int row, int chunk) {
    return (uint32_t)(row * 128 + ((chunk ^ (row & 7)) << 4));
}
// cumulative tiles before row b (row r has NB-r tiles)
__device__ __forceinline__ int triC(int b) { return b * NB - (b * (b - 1)) / 2; }

// ---------------------------------------------------------------- kernel 0
__global__ void initKernel(float* out) {
    int i = blockIdx.x * blockDim.x + threadIdx.x;
    if (i < N_ROWS) g_best[i] = 0ull;
    if (i == 0) out[0] = 0.0f;
}

// ---------------------------------------------------------------- kernel 1: fp32 -> bf16 hi/lo
__global__ void convertKernel(const float* __restrict__ x) {
    size_t i = (size_t)blockIdx.x * blockDim.x + threadIdx.x;
    const size_t n4 = (size_t)N_ROWS * DIMS / 4;
    if (i >= n4) return;
    float4 v = ((const float4*)x)[i];
    __nv_bfloat16 h0 = __float2bfloat16(v.x), h1 = __float2bfloat16(v.y);
    __nv_bfloat16 h2 = __float2bfloat16(v.z), h3 = __float2bfloat16(v.w);
    __nv_bfloat16 l0 = __float2bfloat16(v.x - __bfloat162float(h0));
    __nv_bfloat16 l1 = __float2bfloat16(v.y - __bfloat162float(h1));
    __nv_bfloat16 l2 = __float2bfloat16(v.z - __bfloat162float(h2));
    __nv_bfloat16 l3 = __float2bfloat16(v.w - __bfloat162float(h3));
    ushort4 hp, lp;
    hp.x = *(unsigned short*)&h0; hp.y = *(unsigned short*)&h1;
    hp.z = *(unsigned short*)&h2; hp.w = *(unsigned short*)&h3;
    lp.x = *(unsigned short*)&l0; lp.y = *(unsigned short*)&l1;
    lp.z = *(unsigned short*)&l2; lp.w = *(unsigned short*)&l3;
    ((ushort4*)g_xhi)[i] = hp;
    ((ushort4*)g_xlo)[i] = lp;
}

// ---------------------------------------------------------------- kernel 2: centers + d_ap
__global__ void centersDapKernel(const float* __restrict__ x) {
    int c = blockIdx.x;
    const float4* base = (const float4*)(x + (size_t)c * CHUNK * DIMS);
    const int D4 = DIMS / 4;

    float acc[CHUNK];
    #pragma unroll
    for (int r = 0; r < CHUNK; r++) acc[r] = 0.0f;

    for (int col = threadIdx.x; col < D4; col += blockDim.x) {
        float4 v[CHUNK];
        float4 m = make_float4(0.f, 0.f, 0.f, 0.f);
        #pragma unroll
        for (int r = 0; r < CHUNK; r++) {
            v[r] = base[r * (DIMS / 4) + col];
            m.x += v[r].x; m.y += v[r].y; m.z += v[r].z; m.w += v[r].w;
        }
        m.x *= 0.125f; m.y *= 0.125f; m.z *= 0.125f; m.w *= 0.125f;
        #pragma unroll
        for (int r = 0; r < CHUNK; r++) {
            acc[r] += fabsf(v[r].x - m.x) + fabsf(v[r].y - m.y)
                    + fabsf(v[r].z - m.z) + fabsf(v[r].w - m.w);
        }
    }

    __shared__ float part[CHUNK][8];
    int lane = threadIdx.x & 31, w = threadIdx.x >> 5;
    #pragma unroll
    for (int r = 0; r < CHUNK; r++) {
        float s = acc[r];
        #pragma unroll
        for (int off = 16; off; off >>= 1) s += __shfl_xor_sync(0xFFFFFFFFu, s, off);
        if (lane == 0) part[r][w] = s;
    }
    __syncthreads();
    if (threadIdx.x < CHUNK) {
        float s = 0.f;
        #pragma unroll
        for (int ww = 0; ww < 8; ww++) s += part[threadIdx.x][ww];
        g_dap[c * CHUNK + threadIdx.x] = 0.5f * s * (1.0f / DIMS);
    }
}

// ---------------------------------------------------------------- kernel 3: HMMA sim + fused argmax
// 2-pass split: sim ~= Ahi*Bhi^T + Ahi*Blo^T  (lo*hi term dropped; noise << argmax gaps)
__device__ __forceinline__ void fill_stage(uint32_t sbase, int rowA, int rowB,
                                           int k0, int tid) {
    const __nv_bfloat16* srcs[3] = {
        g_xhi + (size_t)rowA * DIMS,
        g_xhi + (size_t)rowB * DIMS,
        g_xlo + (size_t)rowB * DIMS };
    #pragma unroll
    for (int o = 0; o < 3; o++) {
        uint32_t base = sbase + o * TILE_B;
        const char* g = (const char*)(srcs[o]) + (size_t)k0 * 2;
        #pragma unroll
        for (int c = tid; c < 1024; c += 256) {
            int row = c >> 3, ch = c & 7;
            cpasync16(base + swz(row, ch), g + (size_t)row * (DIMS * 2) + ch * 16);
        }
    }
}

__global__ __launch_bounds__(256, 2) void simArgmaxMma() {
    int bi, bj;
    {
        int t = blockIdx.x;
        float nb5 = NB + 0.5f;
        int b = (int)floorf(nb5 - sqrtf(nb5 * nb5 - 2.0f * (float)t));
        if (b < 0) b = 0;
        if (b > NB - 1) b = NB - 1;
        while (triC(b) > t) b--;
        while (triC(b + 1) <= t) b++;
        bi = b;
        bj = bi + (t - triC(bi));
    }
    const bool diag = (bi == bj);

    extern __shared__ char smem[];
    const uint32_t sb = smem_u32(smem);
    const int tid = threadIdx.x;
    const int lane = tid & 31, warp = tid >> 5;
    const int wr = warp >> 1, wc = warp & 1;   // 4 x 2 warp grid, warp tile 32x64

    const int rowA = bi * TM, rowB = bj * TN;

    float acc[2][8][4];
    #pragma unroll
    for (int mt = 0; mt < 2; mt++)
        #pragma unroll
        for (int nt = 0; nt < 8; nt++)
            #pragma unroll
            for (int e = 0; e < 4; e++) acc[mt][nt][e] = 0.0f;

    const int mi = lane >> 3, r8 = lane & 7;

    fill_stage(sb, rowA, rowB, 0, tid);
    asm volatile("cp.async.commit_group;" ::: "memory");

    #pragma unroll 1
    for (int t = 0; t < NCHUNK; t++) {
        if (t + 1 < NCHUNK) {
            fill_stage(sb + ((t + 1) & 1) * STAGE_B, rowA, rowB, (t + 1) * KC, tid);
            asm volatile("cp.async.commit_group;" ::: "memory");
            asm volatile("cp.async.wait_group 1;" ::: "memory");
        } else {
            asm volatile("cp.async.wait_group 0;" ::: "memory");
        }
        __syncthreads();

        const uint32_t stg = sb + (t & 1) * STAGE_B;
        const uint32_t sAhi = stg;
        const uint32_t sBhi = stg + TILE_B;
        const uint32_t sBlo = stg + 2 * TILE_B;

        #pragma unroll
        for (int ks = 0; ks < 4; ks++) {
            const int chunk = ks * 2 + (mi >> 1);
            uint32_t ahi[2][4], bhi[8][2], blo[8][2];
            #pragma unroll
            for (int mt = 0; mt < 2; mt++) {
                int row = wr * 32 + mt * 16 + (mi & 1) * 8 + r8;
                ldsm_x4(ahi[mt], sAhi + swz(row, chunk));
            }
            #pragma unroll
            for (int np = 0; np < 4; np++) {
                int row = wc * 64 + np * 16 + (mi & 1) * 8 + r8;
                uint32_t th[4], tl[4];
                ldsm_x4(th, sBhi + swz(row, chunk));
                ldsm_x4(tl, sBlo + swz(row, chunk));
                bhi[2 * np][0] = th[0]; bhi[2 * np + 1][0] = th[1];
                bhi[2 * np][1] = th[2]; bhi[2 * np + 1][1] = th[3];
                blo[2 * np][0] = tl[0]; blo[2 * np + 1][0] = tl[1];
                blo[2 * np][1] = tl[2]; blo[2 * np + 1][1] = tl[3];
            }
            #pragma unroll
            for (int mt = 0; mt < 2; mt++)
                #pragma unroll
                for (int nt = 0; nt < 8; nt++) {
                    mma16816(acc[mt][nt], ahi[mt], bhi[nt]);
                    mma16816(acc[mt][nt], ahi[mt], blo[nt]);
                }
        }
        __syncthreads();
    }

    // ---------------- epilogue ----------------
    const int qrow = lane >> 2;            // 0..7
    const int qcol = (lane & 3) * 2;       // 0,2,4,6

    #pragma unroll
    for (int mt = 0; mt < 2; mt++)
        #pragma unroll
        for (int half = 0; half < 2; half++) {
            const int gi = rowA + wr * 32 + mt * 16 + half * 8 + qrow;
            float bv = NEG_INF;
            unsigned bj_ = 0;
            #pragma unroll
            for (int nt = 0; nt < 8; nt++)
                #pragma unroll
                for (int e = 0; e < 2; e++) {
                    const int gj = rowB + wc * 64 + nt * 8 + qcol + e;
                    float v = acc[mt][nt][half * 2 + e];
                    if (diag && ((gi >> 2) == (gj >> 2))) v = NEG_INF;
                    if (v > bv) { bv = v; bj_ = (unsigned)gj; }
                }
            unsigned long long p = packCand(bv, bj_);
            #pragma unroll
            for (int off = 1; off <= 2; off <<= 1) {
                unsigned long long q = __shfl_xor_sync(0xFFFFFFFFu, p, off);
                if (q > p) p = q;
            }
            if ((lane & 3) == 0) atomicMax(&g_best[gi], p);
        }

    if (!diag) {
        unsigned long long* colred = (unsigned long long*)smem;   // 128 cols x 4 warpRows
        #pragma unroll
        for (int nt = 0; nt < 8; nt++)
            #pragma unroll
            for (int e = 0; e < 2; e++) {
                float bv = NEG_INF;
                unsigned br = 0;
                #pragma unroll
                for (int mt = 0; mt < 2; mt++)
                    #pragma unroll
                    for (int half = 0; half < 2; half++) {
                        const int gi = rowA + wr * 32 + mt * 16 + half * 8 + qrow;
                        float v = acc[mt][nt][half * 2 + e];
                        if (v > bv) { bv = v; br = (unsigned)gi; }
                    }
                unsigned long long p = packCand(bv, br);
                #pragma unroll
                for (int off = 4; off <= 16; off <<= 1) {
                    unsigned long long q = __shfl_xor_sync(0xFFFFFFFFu, p, off);
                    if (q > p) p = q;
                }
                if (qrow == 0) {
                    const int lc = wc * 64 + nt * 8 + qcol + e;
                    colred[lc * 4 + wr] = p;
                }
            }
        __syncthreads();
        if (tid < 128) {
            unsigned long long p = colred[tid * 4];
            #pragma unroll
            for (int w = 1; w < 4; w++) {
                unsigned long long q = colred[tid * 4 + w];
                if (q > p) p = q;
            }
            atomicMax(&g_best[rowB + tid], p);
        }
    }
}

// ---------------------------------------------------------------- kernel 4: final
__global__ void finalKernel(const float* __restrict__ x, float* __restrict__ out) {
    const int i = blockIdx.x;
    const unsigned j = 0xFFFFFFFFu - (unsigned)(g_best[i] & 0xFFFFFFFFull);

    const float4* xi = (const float4*)(x + (size_t)i * DIMS);
    const float4* xj = (const float4*)(x + (size_t)j * DIMS);
    const int D4 = DIMS / 4;

    float s = 0.0f;
    for (int c = threadIdx.x; c < D4; c += blockDim.x) {
        float4 a = xi[c];
        float4 b = xj[c];
        s += fabsf(a.x - b.x) + fabsf(a.y - b.y) + fabsf(a.z - b.z) + fabsf(a.w - b.w);
    }

    __shared__ float part[8];
    int lane = threadIdx.x & 31, w = threadIdx.x >> 5;
    #pragma unroll
    for (int off = 16; off; off >>= 1) s += __shfl_xor_sync(0xFFFFFFFFu, s, off);
    if (lane == 0) part[w] = s;
    __syncthreads();
    if (threadIdx.x == 0) {
        float tot = 0.f;
        #pragma unroll
        for (int ww = 0; ww < 8; ww++) tot += part[ww];
        float dan = tot * (1.0f / DIMS);
        atomicAdd(out, 0.125f * g_dap[i] / (dan + 1e-7f));
    }
}

// ----------------------------------------------------------------
extern "C" void kernel_launch(void* const* d_in, const int* in_sizes, int n_in,
                              void* d_out, int out_size) {
    const float* x = (const float*)d_in[0];
    float* out = (float*)d_out;

    cudaFuncSetAttribute(simArgmaxMma, cudaFuncAttributeMaxDynamicSharedMemorySize,
                         SMEM_TOTAL);

    initKernel<<<(N_ROWS + 255) / 256, 256>>>(out);
    convertKernel<<<(N_ROWS * (DIMS / 4) + 255) / 256, 256>>>(x);
    centersDapKernel<<<N_ROWS / CHUNK, 256>>>(x);
    simArgmaxMma<<<NTILES, 256, SMEM_TOTAL>>>();
    finalKernel<<<N_ROWS, 256>>>(x, out);
}

// round 6
// speedup vs baseline: 11.2628x; 2.6926x over previous
#include <cuda_runtime.h>
#include <cuda_fp16.h>
#include <cstdint>

// ---------------------------------------------------------------- constants
#define N_ROWS 8192
#define DIMS   2048
#define CHUNK  8
#define TM 128
#define TN 128
#define KC 64                     // K per smem stage (4 mma k-steps of 16)
#define NB (N_ROWS / TM)          // 64
#define NCHUNK (DIMS / KC)        // 32
#define NTILES (NB * (NB + 1) / 2)  // 2080 upper-triangular tiles

#define TILE_B  (128 * 128)       // 16 KB: 128 rows x 64 fp16 (128B)
#define STAGE_B (2 * TILE_B)      // A, B = 32 KB
#define SMEM_TOTAL (2 * STAGE_B)  // 64 KB double-buffered -> 2 CTAs/SM easily

#define NEG_INF __int_as_float(0xFF800000)

// ---------------------------------------------------------------- scratch
__device__ unsigned long long g_best[N_ROWS];
__device__ float g_dap[N_ROWS];
__device__ __half g_xh[(size_t)N_ROWS * DIMS];

// ---------------------------------------------------------------- helpers
__device__ __forceinline__ uint32_t smem_u32(const void* p) {
    uint32_t a;
    asm("{ .reg .u64 t; cvta.to.shared.u64 t, %1; cvt.u32.u64 %0, t; }" : "=r"(a) : "l"(p));
    return a;
}
__device__ __forceinline__ unsigned long long packCand(float v, unsigned j) {
    unsigned u = __float_as_uint(v);
    u = (u & 0x80000000u) ? ~u : (u | 0x80000000u);
    return ((unsigned long long)u << 32) | (unsigned long long)(0xFFFFFFFFu - j);
}
__device__ __forceinline__ void cpasync16(uint32_t dst, const void* src) {
    asm volatile("cp.async.cg.shared.global [%0], [%1], 16;" :: "r"(dst), "l"(src) : "memory");
}
__device__ __forceinline__ void ldsm_x4(uint32_t* r, uint32_t addr) {
    asm volatile("ldmatrix.sync.aligned.m8n8.x4.shared.b16 {%0,%1,%2,%3}, [%4];"
                 : "=r"(r[0]), "=r"(r[1]), "=r"(r[2]), "=r"(r[3]) : "r"(addr));
}
__device__ __forceinline__ void mma16816(float* d, const uint32_t* a, const uint32_t* b) {
    asm volatile(
        "mma.sync.aligned.m16n8k16.row.col.f32.f16.f16.f32 "
        "{%0,%1,%2,%3}, {%4,%5,%6,%7}, {%8,%9}, {%0,%1,%2,%3};"
        : "+f"(d[0]), "+f"(d[1]), "+f"(d[2]), "+f"(d[3])
        : "r"(a[0]), "r"(a[1]), "r"(a[2]), "r"(a[3]), "r"(b[0]), "r"(b[1]));
}
// swizzled smem byte offset: 128B rows, 8x 16B chunks, XOR by row&7
__device__ __forceinline__ uint32_t swz(int row, int chunk) {
    return (uint32_t)(row * 128 + ((chunk ^ (row & 7)) << 4));
}
// cumulative tiles before row b
__device__ __forceinline__ int triC(int b) { return b * NB - (b * (b - 1)) / 2; }

// ---------------------------------------------------------------- kernel 0
__global__ void initKernel(float* out) {
    int i = blockIdx.x * blockDim.x + threadIdx.x;
    if (i < N_ROWS) g_best[i] = 0ull;
    if (i == 0) out[0] = 0.0f;
}

// ---------------------------------------------------------------- kernel 1: fp32 -> fp16
__global__ void convertKernel(const float* __restrict__ x) {
    size_t i = (size_t)blockIdx.x * blockDim.x + threadIdx.x;
    const size_t n4 = (size_t)N_ROWS * DIMS / 4;
    if (i >= n4) return;
    float4 v = ((const float4*)x)[i];
    __half2 a = __floats2half2_rn(v.x, v.y);
    __half2 b = __floats2half2_rn(v.z, v.w);
    uint2 p;
    p.x = *(uint32_t*)&a;
    p.y = *(uint32_t*)&b;
    ((uint2*)g_xh)[i] = p;
}

// ---------------------------------------------------------------- kernel 2: centers + d_ap
__global__ void centersDapKernel(const float* __restrict__ x) {
    int c = blockIdx.x;
    const float4* base = (const float4*)(x + (size_t)c * CHUNK * DIMS);
    const int D4 = DIMS / 4;

    float acc[CHUNK];
    #pragma unroll
    for (int r = 0; r < CHUNK; r++) acc[r] = 0.0f;

    for (int col = threadIdx.x; col < D4; col += blockDim.x) {
        float4 v[CHUNK];
        float4 m = make_float4(0.f, 0.f, 0.f, 0.f);
        #pragma unroll
        for (int r = 0; r < CHUNK; r++) {
            v[r] = base[r * (DIMS / 4) + col];
            m.x += v[r].x; m.y += v[r].y; m.z += v[r].z; m.w += v[r].w;
        }
        m.x *= 0.125f; m.y *= 0.125f; m.z *= 0.125f; m.w *= 0.125f;
        #pragma unroll
        for (int r = 0; r < CHUNK; r++) {
            acc[r] += fabsf(v[r].x - m.x) + fabsf(v[r].y - m.y)
                    + fabsf(v[r].z - m.z) + fabsf(v[r].w - m.w);
        }
    }

    __shared__ float part[CHUNK][8];
    int lane = threadIdx.x & 31, w = threadIdx.x >> 5;
    #pragma unroll
    for (int r = 0; r < CHUNK; r++) {
        float s = acc[r];
        #pragma unroll
        for (int off = 16; off; off >>= 1) s += __shfl_xor_sync(0xFFFFFFFFu, s, off);
        if (lane == 0) part[r][w] = s;
    }
    __syncthreads();
    if (threadIdx.x < CHUNK) {
        float s = 0.f;
        #pragma unroll
        for (int ww = 0; ww < 8; ww++) s += part[threadIdx.x][ww];
        g_dap[c * CHUNK + threadIdx.x] = 0.5f * s * (1.0f / DIMS);
    }
}

// ---------------------------------------------------------------- kernel 3: fp16 HMMA sim + fused argmax
__device__ __forceinline__ void fill_stage(uint32_t sbase, int rowA, int rowB,
                                           int k0, int tid) {
    const __half* srcs[2] = { g_xh + (size_t)rowA * DIMS, g_xh + (size_t)rowB * DIMS };
    #pragma unroll
    for (int o = 0; o < 2; o++) {
        uint32_t base = sbase + o * TILE_B;
        const char* g = (const char*)(srcs[o]) + (size_t)k0 * 2;
        #pragma unroll
        for (int c = tid; c < 1024; c += 256) {
            int row = c >> 3, ch = c & 7;
            cpasync16(base + swz(row, ch), g + (size_t)row * (DIMS * 2) + ch * 16);
        }
    }
}

__global__ __launch_bounds__(256, 2) void simArgmaxMma() {
    int bi, bj;
    {
        int t = blockIdx.x;
        float nb5 = NB + 0.5f;
        int b = (int)floorf(nb5 - sqrtf(nb5 * nb5 - 2.0f * (float)t));
        if (b < 0) b = 0;
        if (b > NB - 1) b = NB - 1;
        while (triC(b) > t) b--;
        while (triC(b + 1) <= t) b++;
        bi = b;
        bj = bi + (t - triC(bi));
    }
    const bool diag = (bi == bj);

    extern __shared__ char smem[];
    const uint32_t sb = smem_u32(smem);
    const int tid = threadIdx.x;
    const int lane = tid & 31, warp = tid >> 5;
    const int wr = warp >> 1, wc = warp & 1;   // 4 x 2 warp grid, warp tile 32x64

    const int rowA = bi * TM, rowB = bj * TN;

    float acc[2][8][4];
    #pragma unroll
    for (int mt = 0; mt < 2; mt++)
        #pragma unroll
        for (int nt = 0; nt < 8; nt++)
            #pragma unroll
            for (int e = 0; e < 4; e++) acc[mt][nt][e] = 0.0f;

    const int mi = lane >> 3, r8 = lane & 7;

    fill_stage(sb, rowA, rowB, 0, tid);
    asm volatile("cp.async.commit_group;" ::: "memory");

    #pragma unroll 1
    for (int t = 0; t < NCHUNK; t++) {
        if (t + 1 < NCHUNK) {
            fill_stage(sb + ((t + 1) & 1) * STAGE_B, rowA, rowB, (t + 1) * KC, tid);
            asm volatile("cp.async.commit_group;" ::: "memory");
            asm volatile("cp.async.wait_group 1;" ::: "memory");
        } else {
            asm volatile("cp.async.wait_group 0;" ::: "memory");
        }
        __syncthreads();

        const uint32_t stg = sb + (t & 1) * STAGE_B;
        const uint32_t sA = stg;
        const uint32_t sB = stg + TILE_B;

        #pragma unroll
        for (int ks = 0; ks < 4; ks++) {
            const int chunk = ks * 2 + (mi >> 1);
            uint32_t a[2][4], b[8][2];
            #pragma unroll
            for (int mt = 0; mt < 2; mt++) {
                int row = wr * 32 + mt * 16 + (mi & 1) * 8 + r8;
                ldsm_x4(a[mt], sA + swz(row, chunk));
            }
            #pragma unroll
            for (int np = 0; np < 4; np++) {
                int row = wc * 64 + np * 16 + (mi & 1) * 8 + r8;
                uint32_t tb[4];
                ldsm_x4(tb, sB + swz(row, chunk));
                b[2 * np][0] = tb[0]; b[2 * np + 1][0] = tb[1];
                b[2 * np][1] = tb[2]; b[2 * np + 1][1] = tb[3];
            }
            #pragma unroll
            for (int mt = 0; mt < 2; mt++)
                #pragma unroll
                for (int nt = 0; nt < 8; nt++)
                    mma16816(acc[mt][nt], a[mt], b[nt]);
        }
        __syncthreads();
    }

    // ---------------- epilogue ----------------
    const int qrow = lane >> 2;            // 0..7
    const int qcol = (lane & 3) * 2;       // 0,2,4,6

    #pragma unroll
    for (int mt = 0; mt < 2; mt++)
        #pragma unroll
        for (int half = 0; half < 2; half++) {
            const int gi = rowA + wr * 32 + mt * 16 + half * 8 + qrow;
            float bv = NEG_INF;
            unsigned bj_ = 0;
            #pragma unroll
            for (int nt = 0; nt < 8; nt++)
                #pragma unroll
                for (int e = 0; e < 2; e++) {
                    const int gj = rowB + wc * 64 + nt * 8 + qcol + e;
                    float v = acc[mt][nt][half * 2 + e];
                    if (diag && ((gi >> 2) == (gj >> 2))) v = NEG_INF;
                    if (v > bv) { bv = v; bj_ = (unsigned)gj; }
                }
            unsigned long long p = packCand(bv, bj_);
            #pragma unroll
            for (int off = 1; off <= 2; off <<= 1) {
                unsigned long long q = __shfl_xor_sync(0xFFFFFFFFu, p, off);
                if (q > p) p = q;
            }
            if ((lane & 3) == 0) atomicMax(&g_best[gi], p);
        }

    if (!diag) {
        unsigned long long* colred = (unsigned long long*)smem;   // 128 cols x 4 warpRows
        #pragma unroll
        for (int nt = 0; nt < 8; nt++)
            #pragma unroll
            for (int e = 0; e < 2; e++) {
                float bv = NEG_INF;
                unsigned br = 0;
                #pragma unroll
                for (int mt = 0; mt < 2; mt++)
                    #pragma unroll
                    for (int half = 0; half < 2; half++) {
                        const int gi = rowA + wr * 32 + mt * 16 + half * 8 + qrow;
                        float v = acc[mt][nt][half * 2 + e];
                        if (v > bv) { bv = v; br = (unsigned)gi; }
                    }
                unsigned long long p = packCand(bv, br);
                #pragma unroll
                for (int off = 4; off <= 16; off <<= 1) {
                    unsigned long long q = __shfl_xor_sync(0xFFFFFFFFu, p, off);
                    if (q > p) p = q;
                }
                if (qrow == 0) {
                    const int lc = wc * 64 + nt * 8 + qcol + e;
                    colred[lc * 4 + wr] = p;
                }
            }
        __syncthreads();
        if (tid < 128) {
            unsigned long long p = colred[tid * 4];
            #pragma unroll
            for (int w = 1; w < 4; w++) {
                unsigned long long q = colred[tid * 4 + w];
                if (q > p) p = q;
            }
            atomicMax(&g_best[rowB + tid], p);
        }
    }
}

// ---------------------------------------------------------------- kernel 4: final
__global__ void finalKernel(const float* __restrict__ x, float* __restrict__ out) {
    const int i = blockIdx.x;
    const unsigned j = 0xFFFFFFFFu - (unsigned)(g_best[i] & 0xFFFFFFFFull);

    const float4* xi = (const float4*)(x + (size_t)i * DIMS);
    const float4* xj = (const float4*)(x + (size_t)j * DIMS);
    const int D4 = DIMS / 4;

    float s = 0.0f;
    for (int c = threadIdx.x; c < D4; c += blockDim.x) {
        float4 a = xi[c];
        float4 b = xj[c];
        s += fabsf(a.x - b.x) + fabsf(a.y - b.y) + fabsf(a.z - b.z) + fabsf(a.w - b.w);
    }

    __shared__ float part[8];
    int lane = threadIdx.x & 31, w = threadIdx.x >> 5;
    #pragma unroll
    for (int off = 16; off; off >>= 1) s += __shfl_xor_sync(0xFFFFFFFFu, s, off);
    if (lane == 0) part[w] = s;
    __syncthreads();
    if (threadIdx.x == 0) {
        float tot = 0.f;
        #pragma unroll
        for (int ww = 0; ww < 8; ww++) tot += part[ww];
        float dan = tot * (1.0f / DIMS);
        atomicAdd(out, 0.125f * g_dap[i] / (dan + 1e-7f));
    }
}

// ----------------------------------------------------------------
extern "C" void kernel_launch(void* const* d_in, const int* in_sizes, int n_in,
                              void* d_out, int out_size) {
    const float* x = (const float*)d_in[0];
    float* out = (float*)d_out;

    cudaFuncSetAttribute(simArgmaxMma, cudaFuncAttributeMaxDynamicSharedMemorySize,
                         SMEM_TOTAL);

    initKernel<<<(N_ROWS + 255) / 256, 256>>>(out);
    convertKernel<<<(N_ROWS * (DIMS / 4) + 255) / 256, 256>>>(x);
    centersDapKernel<<<N_ROWS / CHUNK, 256>>>(x);
    simArgmaxMma<<<NTILES, 256, SMEM_TOTAL>>>();
    finalKernel<<<N_ROWS, 256>>>(x, out);
}

// round 7
// speedup vs baseline: 11.2962x; 1.0030x over previous
#include <cuda_runtime.h>
#include <cuda_fp16.h>
#include <cstdint>

// ---------------------------------------------------------------- constants
#define N_ROWS 8192
#define DIMS   2048
#define CHUNK  8
#define TM 128
#define TN 128
#define KC 64                     // K per smem stage (4 mma k-steps of 16)
#define NB (N_ROWS / TM)          // 64
#define NCHUNK (DIMS / KC)        // 32
#define NTILES (NB * (NB + 1) / 2)  // 2080 upper-triangular tiles
#define NSTAGE 3

#define TILE_B  (128 * 128)       // 16 KB: 128 rows x 64 fp16 (128B)
#define STAGE_B (2 * TILE_B)      // A, B = 32 KB
#define SMEM_TOTAL (NSTAGE * STAGE_B)  // 96 KB -> still 2 CTAs/SM (114 KB cap)

#define NEG_INF __int_as_float(0xFF800000)

// ---------------------------------------------------------------- scratch
__device__ unsigned long long g_best[N_ROWS];
__device__ float g_dap[N_ROWS];
__device__ __half g_xh[(size_t)N_ROWS * DIMS];

// ---------------------------------------------------------------- helpers
__device__ __forceinline__ uint32_t smem_u32(const void* p) {
    uint32_t a;
    asm("{ .reg .u64 t; cvta.to.shared.u64 t, %1; cvt.u32.u64 %0, t; }" : "=r"(a) : "l"(p));
    return a;
}
__device__ __forceinline__ unsigned long long packCand(float v, unsigned j) {
    unsigned u = __float_as_uint(v);
    u = (u & 0x80000000u) ? ~u : (u | 0x80000000u);
    return ((unsigned long long)u << 32) | (unsigned long long)(0xFFFFFFFFu - j);
}
__device__ __forceinline__ void cpasync16(uint32_t dst, const void* src) {
    asm volatile("cp.async.cg.shared.global [%0], [%1], 16;" :: "r"(dst), "l"(src) : "memory");
}
__device__ __forceinline__ void ldsm_x4(uint32_t* r, uint32_t addr) {
    asm volatile("ldmatrix.sync.aligned.m8n8.x4.shared.b16 {%0,%1,%2,%3}, [%4];"
                 : "=r"(r[0]), "=r"(r[1]), "=r"(r[2]), "=r"(r[3]) : "r"(addr));
}
__device__ __forceinline__ void mma16816(float* d, const uint32_t* a, const uint32_t* b) {
    asm volatile(
        "mma.sync.aligned.m16n8k16.row.col.f32.f16.f16.f32 "
        "{%0,%1,%2,%3}, {%4,%5,%6,%7}, {%8,%9}, {%0,%1,%2,%3};"
        : "+f"(d[0]), "+f"(d[1]), "+f"(d[2]), "+f"(d[3])
        : "r"(a[0]), "r"(a[1]), "r"(a[2]), "r"(a[3]), "r"(b[0]), "r"(b[1]));
}
// swizzled smem byte offset: 128B rows, 8x 16B chunks, XOR by row&7
__device__ __forceinline__ uint32_t swz(int row, int chunk) {
    return (uint32_t)(row * 128 + ((chunk ^ (row & 7)) << 4));
}
// cumulative tiles before row b
__device__ __forceinline__ int triC(int b) { return b * NB - (b * (b - 1)) / 2; }

// ---------------------------------------------------------------- kernel 1: fused prep
// block per chunk of 8 rows: init g_best/out, fp32->fp16 convert, centers + d_ap
__global__ __launch_bounds__(256) void prepKernel(const float* __restrict__ x,
                                                  float* __restrict__ out) {
    const int c = blockIdx.x;                 // 0..1023
    if (threadIdx.x < CHUNK) g_best[c * CHUNK + threadIdx.x] = 0ull;
    if (c == 0 && threadIdx.x == 0) out[0] = 0.0f;

    const float4* base = (const float4*)(x + (size_t)c * CHUNK * DIMS);
    const int D4 = DIMS / 4;

    float acc[CHUNK];
    #pragma unroll
    for (int r = 0; r < CHUNK; r++) acc[r] = 0.0f;

    for (int col = threadIdx.x; col < D4; col += blockDim.x) {
        float4 v[CHUNK];
        float4 m = make_float4(0.f, 0.f, 0.f, 0.f);
        #pragma unroll
        for (int r = 0; r < CHUNK; r++) {
            v[r] = base[r * D4 + col];
            m.x += v[r].x; m.y += v[r].y; m.z += v[r].z; m.w += v[r].w;
        }
        m.x *= 0.125f; m.y *= 0.125f; m.z *= 0.125f; m.w *= 0.125f;
        #pragma unroll
        for (int r = 0; r < CHUNK; r++) {
            acc[r] += fabsf(v[r].x - m.x) + fabsf(v[r].y - m.y)
                    + fabsf(v[r].z - m.z) + fabsf(v[r].w - m.w);
            // fp16 convert + store
            __half2 p0 = __floats2half2_rn(v[r].x, v[r].y);
            __half2 p1 = __floats2half2_rn(v[r].z, v[r].w);
            uint2 pk;
            pk.x = *(uint32_t*)&p0;
            pk.y = *(uint32_t*)&p1;
            ((uint2*)g_xh)[(size_t)(c * CHUNK + r) * D4 + col] = pk;
        }
    }

    __shared__ float part[CHUNK][8];
    int lane = threadIdx.x & 31, w = threadIdx.x >> 5;
    #pragma unroll
    for (int r = 0; r < CHUNK; r++) {
        float s = acc[r];
        #pragma unroll
        for (int off = 16; off; off >>= 1) s += __shfl_xor_sync(0xFFFFFFFFu, s, off);
        if (lane == 0) part[r][w] = s;
    }
    __syncthreads();
    if (threadIdx.x < CHUNK) {
        float s = 0.f;
        #pragma unroll
        for (int ww = 0; ww < 8; ww++) s += part[threadIdx.x][ww];
        g_dap[c * CHUNK + threadIdx.x] = 0.5f * s * (1.0f / DIMS);
    }
}

// ---------------------------------------------------------------- kernel 2: fp16 HMMA sim + fused argmax
__device__ __forceinline__ void fill_stage(uint32_t sbase, int rowA, int rowB,
                                           int k0, int tid) {
    const __half* srcs[2] = { g_xh + (size_t)rowA * DIMS, g_xh + (size_t)rowB * DIMS };
    #pragma unroll
    for (int o = 0; o < 2; o++) {
        uint32_t base = sbase + o * TILE_B;
        const char* g = (const char*)(srcs[o]) + (size_t)k0 * 2;
        #pragma unroll
        for (int c = tid; c < 1024; c += 256) {
            int row = c >> 3, ch = c & 7;
            cpasync16(base + swz(row, ch), g + (size_t)row * (DIMS * 2) + ch * 16);
        }
    }
}

__global__ __launch_bounds__(256, 2) void simArgmaxMma() {
    int bi, bj;
    {
        int t = blockIdx.x;
        float nb5 = NB + 0.5f;
        int b = (int)floorf(nb5 - sqrtf(nb5 * nb5 - 2.0f * (float)t));
        if (b < 0) b = 0;
        if (b > NB - 1) b = NB - 1;
        while (triC(b) > t) b--;
        while (triC(b + 1) <= t) b++;
        bi = b;
        bj = bi + (t - triC(bi));
    }
    const bool diag = (bi == bj);

    extern __shared__ char smem[];
    const uint32_t sb = smem_u32(smem);
    const int tid = threadIdx.x;
    const int lane = tid & 31, warp = tid >> 5;
    const int wr = warp >> 1, wc = warp & 1;   // 4 x 2 warp grid, warp tile 32x64

    const int rowA = bi * TM, rowB = bj * TN;

    float acc[2][8][4];
    #pragma unroll
    for (int mt = 0; mt < 2; mt++)
        #pragma unroll
        for (int nt = 0; nt < 8; nt++)
            #pragma unroll
            for (int e = 0; e < 4; e++) acc[mt][nt][e] = 0.0f;

    const int mi = lane >> 3, r8 = lane & 7;

    // prologue: 2 stages in flight
    fill_stage(sb + 0 * STAGE_B, rowA, rowB, 0, tid);
    asm volatile("cp.async.commit_group;" ::: "memory");
    fill_stage(sb + 1 * STAGE_B, rowA, rowB, KC, tid);
    asm volatile("cp.async.commit_group;" ::: "memory");

    #pragma unroll 1
    for (int t = 0; t < NCHUNK; t++) {
        if (t == NCHUNK - 1) {
            asm volatile("cp.async.wait_group 0;" ::: "memory");
        } else {
            asm volatile("cp.async.wait_group 1;" ::: "memory");
        }
        __syncthreads();

        // issue fill for stage t+2 (overwrites buffer of t-1, which all threads
        // finished before the barrier above)
        if (t + 2 < NCHUNK) {
            fill_stage(sb + ((t + 2) % NSTAGE) * STAGE_B, rowA, rowB, (t + 2) * KC, tid);
            asm volatile("cp.async.commit_group;" ::: "memory");
        }

        const uint32_t stg = sb + (t % NSTAGE) * STAGE_B;
        const uint32_t sA = stg;
        const uint32_t sB = stg + TILE_B;

        #pragma unroll
        for (int ks = 0; ks < 4; ks++) {
            const int chunk = ks * 2 + (mi >> 1);
            uint32_t a[2][4], b[8][2];
            #pragma unroll
            for (int mt = 0; mt < 2; mt++) {
                int row = wr * 32 + mt * 16 + (mi & 1) * 8 + r8;
                ldsm_x4(a[mt], sA + swz(row, chunk));
            }
            #pragma unroll
            for (int np = 0; np < 4; np++) {
                int row = wc * 64 + np * 16 + (mi & 1) * 8 + r8;
                uint32_t tb[4];
                ldsm_x4(tb, sB + swz(row, chunk));
                b[2 * np][0] = tb[0]; b[2 * np + 1][0] = tb[1];
                b[2 * np][1] = tb[2]; b[2 * np + 1][1] = tb[3];
            }
            #pragma unroll
            for (int mt = 0; mt < 2; mt++)
                #pragma unroll
                for (int nt = 0; nt < 8; nt++)
                    mma16816(acc[mt][nt], a[mt], b[nt]);
        }
    }

    // ---------------- epilogue ----------------
    __syncthreads();   // smem reuse below
    const int qrow = lane >> 2;            // 0..7
    const int qcol = (lane & 3) * 2;       // 0,2,4,6

    #pragma unroll
    for (int mt = 0; mt < 2; mt++)
        #pragma unroll
        for (int half = 0; half < 2; half++) {
            const int gi = rowA + wr * 32 + mt * 16 + half * 8 + qrow;
            float bv = NEG_INF;
            unsigned bj_ = 0;
            #pragma unroll
            for (int nt = 0; nt < 8; nt++)
                #pragma unroll
                for (int e = 0; e < 2; e++) {
                    const int gj = rowB + wc * 64 + nt * 8 + qcol + e;
                    float v = acc[mt][nt][half * 2 + e];
                    if (diag && ((gi >> 2) == (gj >> 2))) v = NEG_INF;
                    if (v > bv) { bv = v; bj_ = (unsigned)gj; }
                }
            unsigned long long p = packCand(bv, bj_);
            #pragma unroll
            for (int off = 1; off <= 2; off <<= 1) {
                unsigned long long q = __shfl_xor_sync(0xFFFFFFFFu, p, off);
                if (q > p) p = q;
            }
            if ((lane & 3) == 0) atomicMax(&g_best[gi], p);
        }

    if (!diag) {
        unsigned long long* colred = (unsigned long long*)smem;   // 128 cols x 4 warpRows
        #pragma unroll
        for (int nt = 0; nt < 8; nt++)
            #pragma unroll
            for (int e = 0; e < 2; e++) {
                float bv = NEG_INF;
                unsigned br = 0;
                #pragma unroll
                for (int mt = 0; mt < 2; mt++)
                    #pragma unroll
                    for (int half = 0; half < 2; half++) {
                        const int gi = rowA + wr * 32 + mt * 16 + half * 8 + qrow;
                        float v = acc[mt][nt][half * 2 + e];
                        if (v > bv) { bv = v; br = (unsigned)gi; }
                    }
                unsigned long long p = packCand(bv, br);
                #pragma unroll
                for (int off = 4; off <= 16; off <<= 1) {
                    unsigned long long q = __shfl_xor_sync(0xFFFFFFFFu, p, off);
                    if (q > p) p = q;
                }
                if (qrow == 0) {
                    const int lc = wc * 64 + nt * 8 + qcol + e;
                    colred[lc * 4 + wr] = p;
                }
            }
        __syncthreads();
        if (tid < 128) {
            unsigned long long p = colred[tid * 4];
            #pragma unroll
            for (int w = 1; w < 4; w++) {
                unsigned long long q = colred[tid * 4 + w];
                if (q > p) p = q;
            }
            atomicMax(&g_best[rowB + tid], p);
        }
    }
}

// ---------------------------------------------------------------- kernel 3: final
__global__ void finalKernel(const float* __restrict__ x, float* __restrict__ out) {
    const int i = blockIdx.x;
    const unsigned j = 0xFFFFFFFFu - (unsigned)(g_best[i] & 0xFFFFFFFFull);

    const float4* xi = (const float4*)(x + (size_t)i * DIMS);
    const float4* xj = (const float4*)(x + (size_t)j * DIMS);
    const int D4 = DIMS / 4;

    float s = 0.0f;
    for (int c = threadIdx.x; c < D4; c += blockDim.x) {
        float4 a = xi[c];
        float4 b = xj[c];
        s += fabsf(a.x - b.x) + fabsf(a.y - b.y) + fabsf(a.z - b.z) + fabsf(a.w - b.w);
    }

    __shared__ float part[8];
    int lane = threadIdx.x & 31, w = threadIdx.x >> 5;
    #pragma unroll
    for (int off = 16; off; off >>= 1) s += __shfl_xor_sync(0xFFFFFFFFu, s, off);
    if (lane == 0) part[w] = s;
    __syncthreads();
    if (threadIdx.x == 0) {
        float tot = 0.f;
        #pragma unroll
        for (int ww = 0; ww < 8; ww++) tot += part[ww];
        float dan = tot * (1.0f / DIMS);
        atomicAdd(out, 0.125f * g_dap[i] / (dan + 1e-7f));
    }
}

// ----------------------------------------------------------------
extern "C" void kernel_launch(void* const* d_in, const int* in_sizes, int n_in,
                              void* d_out, int out_size) {
    const float* x = (const float*)d_in[0];
    float* out = (float*)d_out;

    cudaFuncSetAttribute(simArgmaxMma, cudaFuncAttributeMaxDynamicSharedMemorySize,
                         SMEM_TOTAL);

    prepKernel<<<N_ROWS / CHUNK, 256>>>(x, out);
    simArgmaxMma<<<NTILES, 256, SMEM_TOTAL>>>();
    finalKernel<<<N_ROWS, 256>>>(x, out);
}